// round 3
// baseline (speedup 1.0000x reference)
#include <cuda_runtime.h>
#include <cstdint>

#define BB 64
#define MM 2048
#define DD 512
#define BLOCKS_PER_B 32
#define ROWS_PER_BLOCK (MM / BLOCKS_PER_B)   // 64
#define WARPS_PER_BLOCK 8
#define ROWS_PER_WARP (ROWS_PER_BLOCK / WARPS_PER_BLOCK)  // 8

// Per-(batch, chunk) partial: high 32 bits = float bits of squared distance
// (non-negative -> bit pattern monotone), low 32 bits = (MM-1-idx) so that on
// ties the SMALLEST index wins under max (matches jnp.argmax first-occurrence).
__device__ unsigned long long g_part[BB * BLOCKS_PER_B];
// Per-batch arrival counter. Zero-initialized at module load; the finishing
// block resets it to 0 so every graph replay starts from a clean state.
__device__ int g_cnt[BB];

__global__ __launch_bounds__(256) void knn_fused_kernel(
    const float* __restrict__ inputs,   // [BB, DD]
    const float* __restrict__ buffer,   // [BB, MM, DD]
    float* __restrict__ out)            // [BB, DD]
{
    __shared__ float s_in[DD];
    __shared__ unsigned long long s_warp_best[WARPS_PER_BLOCK];
    __shared__ int s_idx;

    const int b     = blockIdx.x / BLOCKS_PER_B;
    const int chunk = blockIdx.x % BLOCKS_PER_B;

    // Stage the query row into smem (2 KB), fully coalesced.
    for (int i = threadIdx.x; i < DD / 4; i += blockDim.x) {
        reinterpret_cast<float4*>(s_in)[i] =
            reinterpret_cast<const float4*>(inputs + (size_t)b * DD)[i];
    }
    __syncthreads();

    const int warp = threadIdx.x >> 5;
    const int lane = threadIdx.x & 31;

    const int m0 = chunk * ROWS_PER_BLOCK + warp * ROWS_PER_WARP;
    const float* base = buffer + ((size_t)b * MM + (size_t)m0) * DD;

    // Deferred accumulation: one accumulator per row, NO shuffles inside the
    // streaming loop. Each i-step issues 8 independent LDG.128 (batched MLP).
    float acc[ROWS_PER_WARP];
#pragma unroll
    for (int r = 0; r < ROWS_PER_WARP; r++) acc[r] = 0.0f;

#pragma unroll
    for (int i = 0; i < 4; i++) {
        const float4 qv = reinterpret_cast<const float4*>(s_in)[lane + i * 32];
        float4 v[ROWS_PER_WARP];
#pragma unroll
        for (int r = 0; r < ROWS_PER_WARP; r++)
            v[r] = __ldg(reinterpret_cast<const float4*>(base + (size_t)r * DD)
                         + lane + i * 32);
#pragma unroll
        for (int r = 0; r < ROWS_PER_WARP; r++) {
            float dx = v[r].x - qv.x;
            float dy = v[r].y - qv.y;
            float dz = v[r].z - qv.z;
            float dw = v[r].w - qv.w;
            acc[r] = fmaf(dx, dx, acc[r]);
            acc[r] = fmaf(dy, dy, acc[r]);
            acc[r] = fmaf(dz, dz, acc[r]);
            acc[r] = fmaf(dw, dw, acc[r]);
        }
    }

    // End-of-loop reductions (once per warp, overlapped with other warps' mem).
    float best_dist = -1.0f;
    int   best_m    = 0;
#pragma unroll
    for (int r = 0; r < ROWS_PER_WARP; r++) {
        float a = acc[r];
#pragma unroll
        for (int o = 16; o > 0; o >>= 1)
            a += __shfl_xor_sync(0xFFFFFFFFu, a, o);
        if (a > best_dist) { best_dist = a; best_m = m0 + r; }
    }

    // Per-warp packed best -> smem, block reduce in thread 0.
    if (lane == 0) {
        s_warp_best[warp] =
            ((unsigned long long)__float_as_uint(best_dist) << 32) |
            (unsigned int)(MM - 1 - best_m);
    }
    __syncthreads();

    if (threadIdx.x == 0) {
        unsigned long long blk = 0ULL;
#pragma unroll
        for (int w = 0; w < WARPS_PER_BLOCK; w++)
            blk = max(blk, s_warp_best[w]);
        g_part[b * BLOCKS_PER_B + chunk] = blk;
        __threadfence();
        int arrived = atomicAdd(&g_cnt[b], 1);
        s_idx = (arrived == BLOCKS_PER_B - 1) ? 1 : 0;
    }
    __syncthreads();

    // Last-arriving block of this batch: reduce all 32 partials + gather.
    if (s_idx) {
        if (warp == 0) {
            unsigned long long v = g_part[b * BLOCKS_PER_B + lane];
#pragma unroll
            for (int o = 16; o > 0; o >>= 1) {
                unsigned long long u = __shfl_xor_sync(0xFFFFFFFFu, v, o);
                v = max(v, u);
            }
            if (lane == 0) {
                s_idx = MM - 1 - (int)(unsigned int)(v & 0xFFFFFFFFu);
                g_cnt[b] = 0;   // reset for next graph replay
            }
        }
        __syncthreads();

        const int idx = s_idx;
        const float4* src = reinterpret_cast<const float4*>(
            buffer + ((size_t)b * MM + (size_t)idx) * DD);
        float4* dst = reinterpret_cast<float4*>(out + (size_t)b * DD);
        // 128 float4 elements; first 128 threads each copy one.
        if (threadIdx.x < DD / 4)
            dst[threadIdx.x] = src[threadIdx.x];
    }
}

extern "C" void kernel_launch(void* const* d_in, const int* in_sizes, int n_in,
                              void* d_out, int out_size)
{
    const float* inputs;
    const float* buffer;
    // inputs has BB*DD = 32768 elems, buffer has BB*MM*DD = 67108864.
    if (in_sizes[0] == BB * DD) {
        inputs = (const float*)d_in[0];
        buffer = (const float*)d_in[1];
    } else {
        inputs = (const float*)d_in[1];
        buffer = (const float*)d_in[0];
    }
    float* out = (float*)d_out;

    knn_fused_kernel<<<BB * BLOCKS_PER_B, 256>>>(inputs, buffer, out);
}

// round 4
// speedup vs baseline: 1.0481x; 1.0481x over previous
#include <cuda_runtime.h>
#include <cstdint>

#define BB 64
#define MM 2048
#define DD 512
#define ROWS_PER_BLOCK 8
#define CHUNKS_PER_B (MM / ROWS_PER_BLOCK)   // 256
#define WARPS_PER_BLOCK 8

// Per-(batch, chunk) partial: high 32 = float bits of squared distance
// (non-negative -> monotone bit pattern), low 32 = (MM-1-idx) so ties pick the
// SMALLEST index under max (matches jnp.argmax first-occurrence).
__device__ unsigned long long g_part[BB * CHUNKS_PER_B];
// Per-batch arrival counter; zero-initialized at load, reset by finisher so
// every graph replay starts clean.
__device__ int g_cnt[BB];

__global__ __launch_bounds__(256, 8) void knn_fused_kernel(
    const float* __restrict__ inputs,   // [BB, DD]
    const float* __restrict__ buffer,   // [BB, MM, DD]
    float* __restrict__ out)            // [BB, DD]
{
    __shared__ float4 s_in[DD / 4];                    // 2 KB query stage
    __shared__ unsigned long long s_warp_best[WARPS_PER_BLOCK];
    __shared__ int s_idx;

    const int b     = blockIdx.x >> 8;                 // / CHUNKS_PER_B
    const int chunk = blockIdx.x & (CHUNKS_PER_B - 1);

    // Stage the query row into smem (fully coalesced, L2-resident source).
    if (threadIdx.x < DD / 4)
        s_in[threadIdx.x] =
            reinterpret_cast<const float4*>(inputs + (size_t)b * DD)[threadIdx.x];
    __syncthreads();

    const int warp = threadIdx.x >> 5;
    const int lane = threadIdx.x & 31;
    const int m    = chunk * ROWS_PER_BLOCK + warp;    // this warp's row

    const float4* row = reinterpret_cast<const float4*>(
        buffer + ((size_t)b * MM + (size_t)m) * DD);

    // Batch all 4 row loads up front (MLP=4 per warp), q comes from smem at
    // compute time so it never occupies long-lived registers.
    float4 v0 = __ldg(row + lane);
    float4 v1 = __ldg(row + lane + 32);
    float4 v2 = __ldg(row + lane + 64);
    float4 v3 = __ldg(row + lane + 96);

    float acc = 0.0f;
    {
        float4 q = s_in[lane];
        float dx = v0.x - q.x, dy = v0.y - q.y, dz = v0.z - q.z, dw = v0.w - q.w;
        acc = fmaf(dx, dx, acc); acc = fmaf(dy, dy, acc);
        acc = fmaf(dz, dz, acc); acc = fmaf(dw, dw, acc);
    }
    {
        float4 q = s_in[lane + 32];
        float dx = v1.x - q.x, dy = v1.y - q.y, dz = v1.z - q.z, dw = v1.w - q.w;
        acc = fmaf(dx, dx, acc); acc = fmaf(dy, dy, acc);
        acc = fmaf(dz, dz, acc); acc = fmaf(dw, dw, acc);
    }
    {
        float4 q = s_in[lane + 64];
        float dx = v2.x - q.x, dy = v2.y - q.y, dz = v2.z - q.z, dw = v2.w - q.w;
        acc = fmaf(dx, dx, acc); acc = fmaf(dy, dy, acc);
        acc = fmaf(dz, dz, acc); acc = fmaf(dw, dw, acc);
    }
    {
        float4 q = s_in[lane + 96];
        float dx = v3.x - q.x, dy = v3.y - q.y, dz = v3.z - q.z, dw = v3.w - q.w;
        acc = fmaf(dx, dx, acc); acc = fmaf(dy, dy, acc);
        acc = fmaf(dz, dz, acc); acc = fmaf(dw, dw, acc);
    }

    // Warp tree-reduce the row distance.
#pragma unroll
    for (int o = 16; o > 0; o >>= 1)
        acc += __shfl_xor_sync(0xFFFFFFFFu, acc, o);

    if (lane == 0) {
        s_warp_best[warp] =
            ((unsigned long long)__float_as_uint(acc) << 32) |
            (unsigned int)(MM - 1 - m);
    }
    __syncthreads();

    if (threadIdx.x == 0) {
        unsigned long long blk = 0ULL;
#pragma unroll
        for (int w = 0; w < WARPS_PER_BLOCK; w++)
            blk = max(blk, s_warp_best[w]);
        g_part[b * CHUNKS_PER_B + chunk] = blk;
        __threadfence();
        int arrived = atomicAdd(&g_cnt[b], 1);
        s_idx = (arrived == CHUNKS_PER_B - 1) ? 1 : 0;
    }
    __syncthreads();

    // Last-arriving block of this batch: reduce 256 partials + gather.
    if (s_idx) {
        if (warp == 0) {
            const unsigned long long* part = g_part + b * CHUNKS_PER_B;
            unsigned long long v = 0ULL;
#pragma unroll
            for (int i = 0; i < CHUNKS_PER_B / 32; i++)
                v = max(v, part[lane + i * 32]);
#pragma unroll
            for (int o = 16; o > 0; o >>= 1) {
                unsigned long long u = __shfl_xor_sync(0xFFFFFFFFu, v, o);
                v = max(v, u);
            }
            if (lane == 0) {
                s_idx = MM - 1 - (int)(unsigned int)(v & 0xFFFFFFFFu);
                g_cnt[b] = 0;   // reset for next graph replay
            }
        }
        __syncthreads();

        const int idx = s_idx;
        const float4* src = reinterpret_cast<const float4*>(
            buffer + ((size_t)b * MM + (size_t)idx) * DD);
        float4* dst = reinterpret_cast<float4*>(out + (size_t)b * DD);
        if (threadIdx.x < DD / 4)
            dst[threadIdx.x] = src[threadIdx.x];
    }
}

extern "C" void kernel_launch(void* const* d_in, const int* in_sizes, int n_in,
                              void* d_out, int out_size)
{
    const float* inputs;
    const float* buffer;
    // inputs has BB*DD = 32768 elems, buffer has BB*MM*DD = 67108864.
    if (in_sizes[0] == BB * DD) {
        inputs = (const float*)d_in[0];
        buffer = (const float*)d_in[1];
    } else {
        inputs = (const float*)d_in[1];
        buffer = (const float*)d_in[0];
    }
    float* out = (float*)d_out;

    knn_fused_kernel<<<BB * CHUNKS_PER_B, 256>>>(inputs, buffer, out);
}